// round 3
// baseline (speedup 1.0000x reference)
#include <cuda_runtime.h>
#include <math.h>
#include <stdint.h>

#define C 16
#define D 512
#define NBLK1 256
#define RPB 256            // rows per pass-1 block
#define NPAIRS (C*(C-1)/2)

// ---------------- device scratch (no allocations allowed) ----------------
// partials: [chunk][c][t] float4 = (sum0, sumsq0, sum1, sumsq1) for dims 2t,2t+1
__device__ float4 g_partial4[NBLK1 * C * 256];   // 16 MB
__device__ int    g_counts[C];
__device__ float  g_mean[C * D];
__device__ float  g_within[C * D];
__device__ double g_pairsum[NPAIRS];
__device__ int    g_ids_is64;

__device__ __forceinline__ int get_id(const int* ids32, int i, int is64) {
    return is64 ? ids32[2 * i] : ids32[i];    // little-endian low word
}

// ---------------- dtype detection + init ----------------
__global__ void k_detect(const int* __restrict__ ids32, int n) {
    if (threadIdx.x == 0) {
        int all_zero = 1;
        int lim = n / 2; if (lim > 128) lim = 128;
        for (int i = 0; i < lim; i++) {
            if (ids32[2 * i + 1] != 0) { all_zero = 0; break; }
        }
        g_ids_is64 = all_zero;
    }
    if (threadIdx.x < C) g_counts[threadIdx.x] = 0;
}

// ---------------- class counts ----------------
__global__ void k_counts(const int* __restrict__ ids32, int n) {
    __shared__ int loc[C];
    if (threadIdx.x < C) loc[threadIdx.x] = 0;
    __syncthreads();
    int is64 = g_ids_is64;
    for (int i = blockIdx.x * blockDim.x + threadIdx.x; i < n;
         i += gridDim.x * blockDim.x) {
        int c = get_id(ids32, i, is64) & (C - 1);
        atomicAdd(&loc[c], 1);
    }
    __syncthreads();
    if (threadIdx.x < C) atomicAdd(&g_counts[threadIdx.x], loc[threadIdx.x]);
}

// ---------------- pass 1: class-sorted register accumulation ----------------
// Block = 256 rows x all 512 dims (float2 per thread). Rows are rank-sorted by
// class deterministically, then each class segment accumulates in registers.
__global__ __launch_bounds__(256) void k_pass1(const float* __restrict__ hidden,
                                               const int* __restrict__ ids32) {
    __shared__ int s_cls[RPB];
    __shared__ int s_order[RPB];
    __shared__ int s_off[C + 1];
    __shared__ int s_hist[C];
    int t = threadIdx.x;
    int rowBase = blockIdx.x * RPB;

    if (t < C) s_hist[t] = 0;
    int myc = get_id(ids32, rowBase + t, g_ids_is64) & (C - 1);
    s_cls[t] = myc;
    __syncthreads();
    atomicAdd(&s_hist[myc], 1);          // counts only (commutative -> deterministic)
    __syncthreads();
    if (t == 0) {
        int acc = 0;
#pragma unroll
        for (int c = 0; c < C; c++) { s_off[c] = acc; acc += s_hist[c]; }
        s_off[C] = acc;
    }
    __syncthreads();
    // deterministic rank: number of earlier rows with same class (broadcast scan)
    int rank = 0;
#pragma unroll 8
    for (int r = 0; r < RPB; r++) {
        int cv = s_cls[r];
        rank += (cv == myc) & (r < t);
    }
    s_order[s_off[myc] + rank] = t;
    __syncthreads();

    const float2* hp = reinterpret_cast<const float2*>(hidden)
                     + (size_t)rowBase * 256 + t;
    float4* out = g_partial4 + (size_t)blockIdx.x * (C * 256) + t;

#pragma unroll 1
    for (int c = 0; c < C; c++) {
        float s0 = 0.f, q0 = 0.f, s1 = 0.f, q1 = 0.f;
        int k   = s_off[c];
        int end = s_off[c + 1];
        for (; k + 3 < end; k += 4) {
            int r0 = s_order[k], r1 = s_order[k + 1];
            int r2 = s_order[k + 2], r3 = s_order[k + 3];
            float2 v0 = hp[(size_t)r0 * 256];
            float2 v1 = hp[(size_t)r1 * 256];
            float2 v2 = hp[(size_t)r2 * 256];
            float2 v3 = hp[(size_t)r3 * 256];
            s0 += v0.x; q0 = fmaf(v0.x, v0.x, q0);
            s1 += v0.y; q1 = fmaf(v0.y, v0.y, q1);
            s0 += v1.x; q0 = fmaf(v1.x, v1.x, q0);
            s1 += v1.y; q1 = fmaf(v1.y, v1.y, q1);
            s0 += v2.x; q0 = fmaf(v2.x, v2.x, q0);
            s1 += v2.y; q1 = fmaf(v2.y, v2.y, q1);
            s0 += v3.x; q0 = fmaf(v3.x, v3.x, q0);
            s1 += v3.y; q1 = fmaf(v3.y, v3.y, q1);
        }
        for (; k < end; k++) {
            int r = s_order[k];
            float2 v = hp[(size_t)r * 256];
            s0 += v.x; q0 = fmaf(v.x, v.x, q0);
            s1 += v.y; q1 = fmaf(v.y, v.y, q1);
        }
        out[c * 256] = make_float4(s0, q0, s1, q1);
    }
}

// ---------------- pass 2: reduce partials -> mean / within ----------------
// One thread per (c, dim-pair); 4-way split fp64 accumulators; coalesced float4.
__global__ __launch_bounds__(64) void k_pass2() {
    int item = blockIdx.x * 64 + threadIdx.x;       // 0 .. 4095
    int c  = item >> 8;
    int t  = item & 255;
    const float4* p = g_partial4 + item;            // chunk stride = 4096 float4

    double s0a=0, s0b=0, s0c=0, s0d=0;
    double q0a=0, q0b=0, q0c=0, q0d=0;
    double s1a=0, s1b=0, s1c=0, s1d=0;
    double q1a=0, q1b=0, q1c=0, q1d=0;
#pragma unroll 4
    for (int ch = 0; ch < NBLK1; ch += 4) {
        float4 v0 = p[(size_t)(ch + 0) * 4096];
        float4 v1 = p[(size_t)(ch + 1) * 4096];
        float4 v2 = p[(size_t)(ch + 2) * 4096];
        float4 v3 = p[(size_t)(ch + 3) * 4096];
        s0a += v0.x; q0a += v0.y; s1a += v0.z; q1a += v0.w;
        s0b += v1.x; q0b += v1.y; s1b += v1.z; q1b += v1.w;
        s0c += v2.x; q0c += v2.y; s1c += v2.z; q1c += v2.w;
        s0d += v3.x; q0d += v3.y; s1d += v3.z; q1d += v3.w;
    }
    double sx0  = (s0a + s0b) + (s0c + s0d);
    double sxx0 = (q0a + q0b) + (q0c + q0d);
    double sx1  = (s1a + s1b) + (s1c + s1d);
    double sxx1 = (q1a + q1b) + (q1c + q1d);

    double cnt = (double)g_counts[c];
    double m0 = sx0 / cnt, m1 = sx1 / cnt;
    int dm = 2 * t;
    g_mean[c * D + dm]       = (float)m0;
    g_mean[c * D + dm + 1]   = (float)m1;
    g_within[c * D + dm]     = (float)(sxx0 - sx0 * m0);
    g_within[c * D + dm + 1] = (float)(sxx1 - sx1 * m1);
}

// ---------------- fp32 Lentz continued fraction for betainc ----------------
__device__ float betacf_f(float a, float b, float x) {
    const float FPMIN = 1e-30f;
    float qab = a + b, qap = a + 1.f, qam = a - 1.f;
    float cc = 1.f;
    float dd = 1.f - qab * x / qap;
    if (fabsf(dd) < FPMIN) dd = FPMIN;
    dd = 1.f / dd;
    float h = dd;
    for (int m = 1; m <= 250; m++) {
        float fm = (float)m, m2 = 2.f * fm;
        float aa = fm * (b - fm) * x / ((qam + m2) * (a + m2));
        dd = 1.f + aa * dd; if (fabsf(dd) < FPMIN) dd = FPMIN;
        cc = 1.f + aa / cc; if (fabsf(cc) < FPMIN) cc = FPMIN;
        dd = 1.f / dd;
        h *= dd * cc;
        aa = -(a + fm) * (qab + fm) * x / ((a + m2) * (qap + m2));
        dd = 1.f + aa * dd; if (fabsf(dd) < FPMIN) dd = FPMIN;
        cc = 1.f + aa / cc; if (fabsf(cc) < FPMIN) cc = FPMIN;
        dd = 1.f / dd;
        float del = dd * cc;
        h *= del;
        if (fabsf(del - 1.f) < 1e-7f) break;
    }
    return h;
}

// ---------------- pair kernel: x -> sort -> betainc(top-K) -> sum log ------
__global__ __launch_bounds__(D) void k_pairs(const int* __restrict__ dptr) {
    __shared__ float sx[D];
    __shared__ float sred[D];
    __shared__ float s_lnB;
    int t = threadIdx.x;

    int bid = blockIdx.x;
    int i = 0, rem = bid;
    while (rem >= C - 1 - i) { rem -= C - 1 - i; i++; }
    int j = i + 1 + rem;

    float ni = (float)g_counts[i], nj = (float)g_counts[j];
    float pc = ni + nj;
    float d2 = pc - 2.f;
    if (d2 == 0.f) d2 = 1e-5f;
    float b = d2 * 0.5f;

    if (t == 0) {
        double bd = (double)b;
        s_lnB = (float)(lgamma(0.5) + lgamma(bd) - lgamma(0.5 + bd));
    }

    float mi = g_mean[i * D + t],  mj = g_mean[j * D + t];
    float wi = g_within[i * D + t], wj = g_within[j * D + t];
    float hd   = (mi - mj) * 0.5f;
    float betw = hd * hd * pc;
    float x = betw / (betw + wi + wj);
    x = fminf(fmaxf(x, 1e-37f), 1.f - 1e-5f);
    sx[t] = x;
    __syncthreads();

    for (int k = 2; k <= D; k <<= 1) {
        for (int jj = k >> 1; jj > 0; jj >>= 1) {
            int ixj = t ^ jj;
            if (ixj > t) {
                float a0 = sx[t], b0 = sx[ixj];
                bool desc = ((t & k) == 0);
                if (desc ? (a0 < b0) : (a0 > b0)) { sx[t] = b0; sx[ixj] = a0; }
            }
            __syncthreads();
        }
    }

    int K = 64;
    if (dptr) {
        int kv = dptr[0];
        if (kv >= 1 && kv <= D) K = kv;
    }

    const float a = 0.5f;
    float val = 0.f;
    if (t < K) {
        float xv  = sx[t];
        float lnB = s_lnB;
        float lbt = a * logf(xv) + b * log1pf(-xv) - lnB;
        float thresh = (a + 1.f) / (a + b + 2.f);
        float logI;
        if (xv < thresh) {
            float cf = betacf_f(a, b, xv);
            if (cf < 1e-30f) cf = 1e-30f;
            logI = lbt + logf(cf) - logf(a);
        } else {
            float cf   = betacf_f(b, a, 1.f - xv);
            float tail = expf(lbt) * cf / b;
            if (tail > 0.99999994f) tail = 0.99999994f;
            logI = log1pf(-tail);
        }
        val = logI;
    }
    sred[t] = val;
    __syncthreads();
    for (int s = D / 2; s > 0; s >>= 1) {
        if (t < s) sred[t] += sred[t + s];
        __syncthreads();
    }
    if (t == 0) g_pairsum[bid] = (double)sred[0];
}

// ---------------- final deterministic scalar reduce ----------------
__global__ void k_final(float* out) {
    if (threadIdx.x == 0) {
        double tot = 0.0;
        for (int p = 0; p < NPAIRS; p++) tot += g_pairsum[p];
        out[0] = (float)(-tot);
    }
}

// ---------------- launch ----------------
extern "C" void kernel_launch(void* const* d_in, const int* in_sizes, int n_in,
                              void* d_out, int out_size) {
    const float* hidden = (const float*)d_in[0];
    const int*   ids32  = (const int*)d_in[1];
    const int*   dptr   = (n_in > 2) ? (const int*)d_in[2] : nullptr;

    int N = in_sizes[0] / D;            // 65536

    k_detect<<<1, 32>>>(ids32, N);
    k_counts<<<64, 256>>>(ids32, N);
    k_pass1 <<<NBLK1, 256>>>(hidden, ids32);
    k_pass2 <<<(C * 256) / 64, 64>>>();
    k_pairs <<<NPAIRS, D>>>(dptr);
    k_final <<<1, 32>>>((float*)d_out);
}

// round 4
// speedup vs baseline: 1.4285x; 1.4285x over previous
#include <cuda_runtime.h>
#include <math.h>
#include <stdint.h>

#define C 16
#define D 512
#define NBLK1 256
#define RPB 256            // rows per pass-1 block
#define NPAIRS (C*(C-1)/2)

// ---------------- device scratch (no allocations allowed) ----------------
// partials: [chunk][c][t] float4 = (sum0, sumsq0, sum1, sumsq1) for dims 2t,2t+1
__device__ float4  g_partial4[NBLK1 * C * 256];   // 16 MB
__device__ double4 g_p2[16 * 4096];               // 2 MB intermediate
__device__ int     g_counts[C];
__device__ float   g_mean[C * D];
__device__ float   g_within[C * D];
__device__ double  g_pairsum[NPAIRS];
__device__ int     g_ids_is64;

__device__ __forceinline__ int get_id(const int* ids32, int i, int is64) {
    return is64 ? ids32[2 * i] : ids32[i];    // little-endian low word
}

// ---------------- dtype detection + init ----------------
__global__ void k_detect(const int* __restrict__ ids32, int n) {
    if (threadIdx.x == 0) {
        int all_zero = 1;
        int lim = n / 2; if (lim > 128) lim = 128;
        for (int i = 0; i < lim; i++) {
            if (ids32[2 * i + 1] != 0) { all_zero = 0; break; }
        }
        g_ids_is64 = all_zero;
    }
    if (threadIdx.x < C) g_counts[threadIdx.x] = 0;
}

// ---------------- class counts ----------------
__global__ void k_counts(const int* __restrict__ ids32, int n) {
    __shared__ int loc[C];
    if (threadIdx.x < C) loc[threadIdx.x] = 0;
    __syncthreads();
    int is64 = g_ids_is64;
    for (int i = blockIdx.x * blockDim.x + threadIdx.x; i < n;
         i += gridDim.x * blockDim.x) {
        int c = get_id(ids32, i, is64) & (C - 1);
        atomicAdd(&loc[c], 1);
    }
    __syncthreads();
    if (threadIdx.x < C) atomicAdd(&g_counts[threadIdx.x], loc[threadIdx.x]);
}

// ---------------- pass 1: register accumulators + block-uniform switch ------
// Thread t owns dims (2t, 2t+1). 16-class accumulators live in registers;
// class selection is a block-uniform switch (no divergence), streaming loads
// stay unconditional so the compiler keeps MLP high. No SMEM in hot loop.
#define ACC_CASE(cc)                                          \
    case cc:                                                  \
        s0[cc] += v.x; q0[cc] = fmaf(v.x, v.x, q0[cc]);       \
        s1[cc] += v.y; q1[cc] = fmaf(v.y, v.y, q1[cc]);       \
        break;

__global__ __launch_bounds__(256) void k_pass1(const float* __restrict__ hidden,
                                               const int* __restrict__ ids32) {
    __shared__ int s_cls[RPB];
    int t = threadIdx.x;
    int rowBase = blockIdx.x * RPB;
    s_cls[t] = get_id(ids32, rowBase + t, g_ids_is64) & (C - 1);
    __syncthreads();

    float s0[C], q0[C], s1[C], q1[C];
#pragma unroll
    for (int c = 0; c < C; c++) { s0[c] = q0[c] = s1[c] = q1[c] = 0.f; }

    const float2* hp = reinterpret_cast<const float2*>(hidden)
                     + (size_t)rowBase * 256 + t;
#pragma unroll 4
    for (int r = 0; r < RPB; r++) {
        float2 v = hp[(size_t)r * 256];
        int c = s_cls[r];
        switch (c) {
            ACC_CASE(0)  ACC_CASE(1)  ACC_CASE(2)  ACC_CASE(3)
            ACC_CASE(4)  ACC_CASE(5)  ACC_CASE(6)  ACC_CASE(7)
            ACC_CASE(8)  ACC_CASE(9)  ACC_CASE(10) ACC_CASE(11)
            ACC_CASE(12) ACC_CASE(13) ACC_CASE(14) ACC_CASE(15)
        }
    }

    float4* out = g_partial4 + (size_t)blockIdx.x * (C * 256) + t;
#pragma unroll
    for (int c = 0; c < C; c++)
        out[c * 256] = make_float4(s0[c], q0[c], s1[c], q1[c]);
}

// ---------------- pass 2a: coalesced chunk-group reduction ----------------
// block (ig, cg): threads cover 256 consecutive items; each sums 16 chunks.
__global__ __launch_bounds__(256) void k_pass2a() {
    int ig = blockIdx.x & 15;
    int cg = blockIdx.x >> 4;
    int item = ig * 256 + threadIdx.x;        // 0..4095
    const float4* p = g_partial4 + item;
    double sx0 = 0, qq0 = 0, sx1 = 0, qq1 = 0;
#pragma unroll
    for (int k = 0; k < 16; k++) {
        float4 v = p[(size_t)(cg * 16 + k) * 4096];
        sx0 += v.x; qq0 += v.y; sx1 += v.z; qq1 += v.w;
    }
    g_p2[cg * 4096 + item] = make_double4(sx0, qq0, sx1, qq1);
}

// ---------------- pass 2b: final group reduction -> mean / within ----------
__global__ __launch_bounds__(256) void k_pass2b() {
    int item = blockIdx.x * 256 + threadIdx.x;   // 0..4095
    double sx0 = 0, qq0 = 0, sx1 = 0, qq1 = 0;
#pragma unroll
    for (int g = 0; g < 16; g++) {
        double4 v = g_p2[g * 4096 + item];
        sx0 += v.x; qq0 += v.y; sx1 += v.z; qq1 += v.w;
    }
    int c = item >> 8;
    int t = item & 255;
    double cnt = (double)g_counts[c];
    double m0 = sx0 / cnt, m1 = sx1 / cnt;
    int dm = 2 * t;
    g_mean[c * D + dm]       = (float)m0;
    g_mean[c * D + dm + 1]   = (float)m1;
    g_within[c * D + dm]     = (float)(qq0 - sx0 * m0);
    g_within[c * D + dm + 1] = (float)(qq1 - sx1 * m1);
}

// ---------------- fp32 Lentz continued fraction for betainc ----------------
__device__ float betacf_f(float a, float b, float x) {
    const float FPMIN = 1e-30f;
    float qab = a + b, qap = a + 1.f, qam = a - 1.f;
    float cc = 1.f;
    float dd = 1.f - qab * x / qap;
    if (fabsf(dd) < FPMIN) dd = FPMIN;
    dd = 1.f / dd;
    float h = dd;
    for (int m = 1; m <= 250; m++) {
        float fm = (float)m, m2 = 2.f * fm;
        float aa = fm * (b - fm) * x / ((qam + m2) * (a + m2));
        dd = 1.f + aa * dd; if (fabsf(dd) < FPMIN) dd = FPMIN;
        cc = 1.f + aa / cc; if (fabsf(cc) < FPMIN) cc = FPMIN;
        dd = 1.f / dd;
        h *= dd * cc;
        aa = -(a + fm) * (qab + fm) * x / ((a + m2) * (qap + m2));
        dd = 1.f + aa * dd; if (fabsf(dd) < FPMIN) dd = FPMIN;
        cc = 1.f + aa / cc; if (fabsf(cc) < FPMIN) cc = FPMIN;
        dd = 1.f / dd;
        float del = dd * cc;
        h *= del;
        if (fabsf(del - 1.f) < 1e-7f) break;
    }
    return h;
}

// ---------------- pair kernel: x -> sort -> betainc(top-K) -> sum log ------
__global__ __launch_bounds__(D) void k_pairs(const int* __restrict__ dptr) {
    __shared__ float sx[D];
    __shared__ float sred[D];
    __shared__ float s_lnB;
    int t = threadIdx.x;

    int bid = blockIdx.x;
    int i = 0, rem = bid;
    while (rem >= C - 1 - i) { rem -= C - 1 - i; i++; }
    int j = i + 1 + rem;

    float ni = (float)g_counts[i], nj = (float)g_counts[j];
    float pc = ni + nj;
    float d2 = pc - 2.f;
    if (d2 == 0.f) d2 = 1e-5f;
    float b = d2 * 0.5f;

    if (t == 0) {
        double bd = (double)b;
        s_lnB = (float)(lgamma(0.5) + lgamma(bd) - lgamma(0.5 + bd));
    }

    float mi = g_mean[i * D + t],  mj = g_mean[j * D + t];
    float wi = g_within[i * D + t], wj = g_within[j * D + t];
    float hd   = (mi - mj) * 0.5f;
    float betw = hd * hd * pc;
    float x = betw / (betw + wi + wj);
    x = fminf(fmaxf(x, 1e-37f), 1.f - 1e-5f);
    sx[t] = x;
    __syncthreads();

    for (int k = 2; k <= D; k <<= 1) {
        for (int jj = k >> 1; jj > 0; jj >>= 1) {
            int ixj = t ^ jj;
            if (ixj > t) {
                float a0 = sx[t], b0 = sx[ixj];
                bool desc = ((t & k) == 0);
                if (desc ? (a0 < b0) : (a0 > b0)) { sx[t] = b0; sx[ixj] = a0; }
            }
            __syncthreads();
        }
    }

    int K = 64;
    if (dptr) {
        int kv = dptr[0];
        if (kv >= 1 && kv <= D) K = kv;
    }

    const float a = 0.5f;
    float val = 0.f;
    if (t < K) {
        float xv  = sx[t];
        float lnB = s_lnB;
        float lbt = a * logf(xv) + b * log1pf(-xv) - lnB;
        float thresh = (a + 1.f) / (a + b + 2.f);
        float logI;
        if (xv < thresh) {
            float cf = betacf_f(a, b, xv);
            if (cf < 1e-30f) cf = 1e-30f;
            logI = lbt + logf(cf) - logf(a);
        } else {
            float cf   = betacf_f(b, a, 1.f - xv);
            float tail = expf(lbt) * cf / b;
            if (tail > 0.99999994f) tail = 0.99999994f;
            logI = log1pf(-tail);
        }
        val = logI;
    }
    sred[t] = val;
    __syncthreads();
    for (int s = D / 2; s > 0; s >>= 1) {
        if (t < s) sred[t] += sred[t + s];
        __syncthreads();
    }
    if (t == 0) g_pairsum[bid] = (double)sred[0];
}

// ---------------- final deterministic scalar reduce ----------------
__global__ void k_final(float* out) {
    if (threadIdx.x == 0) {
        double tot = 0.0;
        for (int p = 0; p < NPAIRS; p++) tot += g_pairsum[p];
        out[0] = (float)(-tot);
    }
}

// ---------------- launch ----------------
extern "C" void kernel_launch(void* const* d_in, const int* in_sizes, int n_in,
                              void* d_out, int out_size) {
    const float* hidden = (const float*)d_in[0];
    const int*   ids32  = (const int*)d_in[1];
    const int*   dptr   = (n_in > 2) ? (const int*)d_in[2] : nullptr;

    int N = in_sizes[0] / D;            // 65536

    k_detect<<<1, 32>>>(ids32, N);
    k_counts<<<64, 256>>>(ids32, N);
    k_pass1 <<<NBLK1, 256>>>(hidden, ids32);
    k_pass2a<<<256, 256>>>();
    k_pass2b<<<16, 256>>>();
    k_pairs <<<NPAIRS, D>>>(dptr);
    k_final <<<1, 32>>>((float*)d_out);
}

// round 6
// speedup vs baseline: 2.2804x; 1.5963x over previous
#include <cuda_runtime.h>
#include <math.h>
#include <stdint.h>

#define C 16
#define D 512
#define CHUNK_ROWS 256
#define DPB 256            // dims per block in pass 1
#define NPAIRS (C*(C-1)/2)
#define NCHUNK 256         // row chunks (N=65536 / 256)
#define PBLK (NCHUNK*2)    // pass-1 partial blocks = 512
#define GRPS 32            // stage-A groups
#define CPG (NCHUNK/GRPS)  // CHUNKS per group = 8

// ---------------- device scratch (no allocations allowed) ----------------
__device__ float2 g_partial[PBLK * C * DPB];     // [blk][c][t] (sum,sumsq) 16 MB
__device__ float2 g_pA[GRPS * C * D];            // stage-A partials 2 MB
__device__ int    g_counts[C];
__device__ float  g_mean[C * D];
__device__ float  g_within[C * D];
__device__ double g_pairsum[NPAIRS];
__device__ int    g_ids_is64;

__device__ __forceinline__ int get_id(const int* ids32, int i, int is64) {
    return is64 ? ids32[2 * i] : ids32[i];    // little-endian low word
}

// ---------------- dtype detection (parallel) + init ----------------
__global__ void k_detect(const int* __restrict__ ids32, int n) {
    __shared__ int s_any;
    int t = threadIdx.x;
    if (t == 0) s_any = 0;
    __syncthreads();
    int lim = n / 2; if (lim > 128) lim = 128;
    if (t < lim && ids32[2 * t + 1] != 0) atomicOr(&s_any, 1);
    __syncthreads();
    if (t == 0) g_ids_is64 = (s_any == 0);
    if (t < C) g_counts[t] = 0;
}

// ---------------- class counts ----------------
__global__ void k_counts(const int* __restrict__ ids32, int n) {
    __shared__ int loc[C];
    if (threadIdx.x < C) loc[threadIdx.x] = 0;
    __syncthreads();
    int is64 = g_ids_is64;
    for (int i = blockIdx.x * blockDim.x + threadIdx.x; i < n;
         i += gridDim.x * blockDim.x) {
        int c = get_id(ids32, i, is64) & (C - 1);
        atomicAdd(&loc[c], 1);
    }
    __syncthreads();
    if (threadIdx.x < C) atomicAdd(&g_counts[threadIdx.x], loc[threadIdx.x]);
}

// ---------------- pass 1: SMEM RMW accumulation (proven R2 geometry) -------
// block = (chunk of 256 rows) x (half of the 512 dims). Thread t owns one dim;
// acc index is computed (no branches), bank-conflict free.
__global__ __launch_bounds__(256) void k_pass1(const float* __restrict__ hidden,
                                               const int* __restrict__ ids32) {
    __shared__ float2 acc[C * DPB];           // 32 KB
    __shared__ int cls[CHUNK_ROWS];
    int t = threadIdx.x;
    int half  = blockIdx.x & 1;
    int chunk = blockIdx.x >> 1;
    int rowBase = chunk * CHUNK_ROWS;

    for (int i = t; i < C * DPB; i += blockDim.x) acc[i] = make_float2(0.f, 0.f);
    cls[t] = get_id(ids32, rowBase + t, g_ids_is64) & (C - 1);
    __syncthreads();

    int dim = half * DPB + t;
    const float* p = hidden + (size_t)rowBase * D + dim;
#pragma unroll 4
    for (int r = 0; r < CHUNK_ROWS; r++) {
        int c = cls[r];
        float v = p[(size_t)r * D];
        float2 a = acc[c * DPB + t];
        a.x += v;
        a.y = fmaf(v, v, a.y);
        acc[c * DPB + t] = a;
    }
    __syncthreads();

    float2* out = g_partial + (size_t)blockIdx.x * (C * DPB);
    for (int i = t; i < C * DPB; i += blockDim.x) out[i] = acc[i];
}

// ---------------- pass 2 stage A: wide coalesced partial reduction ---------
// item = c*512 + dim  (8192 items, float2 each). 32 groups x 8 CHUNKS each
// (chunk -> block index chunk*2+half). Loads coalesced across item.
__global__ __launch_bounds__(256) void k_pass2a() {
    int gid  = blockIdx.x * 256 + threadIdx.x;     // 0 .. 262143
    int item = gid & (C * D - 1);                  // 0 .. 8191
    int grp  = gid >> 13;                          // 0 .. 31
    int c    = item >> 9;
    int dim  = item & (D - 1);
    int half = dim >> 8;
    int t    = dim & (DPB - 1);
    const float2* p = g_partial + (size_t)c * DPB + t;
    float sx = 0.f, qq = 0.f;
#pragma unroll
    for (int k = 0; k < CPG; k++) {
        int chunk = grp * CPG + k;                 // 0 .. 255
        int blk   = (chunk << 1) | half;           // 0 .. 511
        float2 v = p[(size_t)blk * (C * DPB)];
        sx += v.x; qq += v.y;
    }
    g_pA[grp * (C * D) + item] = make_float2(sx, qq);
}

// ---------------- pass 2 stage B: fp64 final -> mean / within --------------
__global__ __launch_bounds__(256) void k_pass2b() {
    int item = blockIdx.x * 256 + threadIdx.x;     // 0 .. 8191
    double sx = 0.0, qq = 0.0;
#pragma unroll
    for (int g = 0; g < GRPS; g++) {
        float2 v = g_pA[g * (C * D) + item];
        sx += (double)v.x; qq += (double)v.y;
    }
    int c = item >> 9;
    double cnt  = (double)g_counts[c];
    double mean = sx / cnt;
    g_mean[item]   = (float)mean;
    g_within[item] = (float)(qq - sx * mean);
}

// ---------------- fp32 Lentz continued fraction for betainc ----------------
__device__ float betacf_f(float a, float b, float x) {
    const float FPMIN = 1e-30f;
    float qab = a + b, qap = a + 1.f, qam = a - 1.f;
    float cc = 1.f;
    float dd = 1.f - qab * x / qap;
    if (fabsf(dd) < FPMIN) dd = FPMIN;
    dd = 1.f / dd;
    float h = dd;
    for (int m = 1; m <= 250; m++) {
        float fm = (float)m, m2 = 2.f * fm;
        float aa = fm * (b - fm) * x / ((qam + m2) * (a + m2));
        dd = 1.f + aa * dd; if (fabsf(dd) < FPMIN) dd = FPMIN;
        cc = 1.f + aa / cc; if (fabsf(cc) < FPMIN) cc = FPMIN;
        dd = 1.f / dd;
        h *= dd * cc;
        aa = -(a + fm) * (qab + fm) * x / ((a + m2) * (qap + m2));
        dd = 1.f + aa * dd; if (fabsf(dd) < FPMIN) dd = FPMIN;
        cc = 1.f + aa / cc; if (fabsf(cc) < FPMIN) cc = FPMIN;
        dd = 1.f / dd;
        float del = dd * cc;
        h *= del;
        if (fabsf(del - 1.f) < 1e-7f) break;
    }
    return h;
}

// ---------------- pair kernel: x -> sort -> betainc(top-K) -> sum log ------
__global__ __launch_bounds__(D) void k_pairs(const int* __restrict__ dptr) {
    __shared__ float sx[D];
    __shared__ float sred[D];
    __shared__ float s_lnB;
    int t = threadIdx.x;

    int bid = blockIdx.x;
    int i = 0, rem = bid;
    while (rem >= C - 1 - i) { rem -= C - 1 - i; i++; }
    int j = i + 1 + rem;

    float ni = (float)g_counts[i], nj = (float)g_counts[j];
    float pc = ni + nj;
    float d2 = pc - 2.f;
    if (d2 == 0.f) d2 = 1e-5f;
    float b = d2 * 0.5f;

    if (t == 0) {
        double bd = (double)b;
        s_lnB = (float)(lgamma(0.5) + lgamma(bd) - lgamma(0.5 + bd));
    }

    float mi = g_mean[i * D + t],  mj = g_mean[j * D + t];
    float wi = g_within[i * D + t], wj = g_within[j * D + t];
    float hd   = (mi - mj) * 0.5f;
    float betw = hd * hd * pc;
    float x = betw / (betw + wi + wj);
    x = fminf(fmaxf(x, 1e-37f), 1.f - 1e-5f);
    sx[t] = x;
    __syncthreads();

    for (int k = 2; k <= D; k <<= 1) {
        for (int jj = k >> 1; jj > 0; jj >>= 1) {
            int ixj = t ^ jj;
            if (ixj > t) {
                float a0 = sx[t], b0 = sx[ixj];
                bool desc = ((t & k) == 0);
                if (desc ? (a0 < b0) : (a0 > b0)) { sx[t] = b0; sx[ixj] = a0; }
            }
            __syncthreads();
        }
    }

    int K = 64;
    if (dptr) {
        int kv = dptr[0];
        if (kv >= 1 && kv <= D) K = kv;
    }

    const float a = 0.5f;
    float val = 0.f;
    if (t < K) {
        float xv  = sx[t];
        float lnB = s_lnB;
        float lbt = a * logf(xv) + b * log1pf(-xv) - lnB;
        float thresh = (a + 1.f) / (a + b + 2.f);
        float logI;
        if (xv < thresh) {
            float cf = betacf_f(a, b, xv);
            if (cf < 1e-30f) cf = 1e-30f;
            logI = lbt + logf(cf) - logf(a);
        } else {
            float cf   = betacf_f(b, a, 1.f - xv);
            float tail = expf(lbt) * cf / b;
            if (tail > 0.99999994f) tail = 0.99999994f;
            logI = log1pf(-tail);
        }
        val = logI;
    }
    sred[t] = val;
    __syncthreads();
    for (int s = D / 2; s > 0; s >>= 1) {
        if (t < s) sred[t] += sred[t + s];
        __syncthreads();
    }
    if (t == 0) g_pairsum[bid] = (double)sred[0];
}

// ---------------- final scalar reduce (parallel, fixed tree order) ---------
__global__ void k_final(float* out) {
    __shared__ double sr[128];
    int t = threadIdx.x;
    sr[t] = (t < NPAIRS) ? g_pairsum[t] : 0.0;
    __syncthreads();
    for (int s = 64; s > 0; s >>= 1) {
        if (t < s) sr[t] += sr[t + s];
        __syncthreads();
    }
    if (t == 0) out[0] = (float)(-sr[0]);
}

// ---------------- launch ----------------
extern "C" void kernel_launch(void* const* d_in, const int* in_sizes, int n_in,
                              void* d_out, int out_size) {
    const float* hidden = (const float*)d_in[0];
    const int*   ids32  = (const int*)d_in[1];
    const int*   dptr   = (n_in > 2) ? (const int*)d_in[2] : nullptr;

    int N = in_sizes[0] / D;            // 65536

    k_detect<<<1, 128>>>(ids32, N);
    k_counts<<<128, 256>>>(ids32, N);
    k_pass1 <<<PBLK, 256>>>(hidden, ids32);
    k_pass2a<<<(GRPS * C * D) / 256, 256>>>();
    k_pass2b<<<(C * D) / 256, 256>>>();
    k_pairs <<<NPAIRS, D>>>(dptr);
    k_final <<<1, 128>>>((float*)d_out);
}